// round 10
// baseline (speedup 1.0000x reference)
#include <cuda_runtime.h>
#include <math.h>

#define B_SZ   128
#define Q_SZ   8
#define BDIM   512

#define U_STRIDE 1152

// SMEM layout (floats)
#define U_OFF   0
#define U_SIZE  (32 * U_STRIDE)             // 36864
#define WV_OFF  U_SIZE                       // Wv  [32][10][8] = 2560 (accumulated, log2e-scaled)
#define S_OFF   (WV_OFF + 2560)              // S_s [32][10][8] = 2560 (iter0: [32][8])
#define SB_OFF  (S_OFF + 2560)               // s_b [10][16] = 160 (final squashed v)
#define VB_OFF  (SB_OFF + 160)               // v_b [10][16] = 160 (log2e-scaled v)
#define SMEM_FLOATS (VB_OFF + 160)
#define SMEM_BYTES  (SMEM_FLOATS * 4)

#define LOG2E 1.4426950408889634f

typedef unsigned long long u64p;             // packed f32x2

__device__ __forceinline__ u64p pk2(float lo, float hi) {
    u64p r; asm("mov.b64 %0, {%1, %2};" : "=l"(r) : "f"(lo), "f"(hi)); return r;
}
__device__ __forceinline__ void upk2(u64p v, float& lo, float& hi) {
    asm("mov.b64 {%0, %1}, %2;" : "=f"(lo), "=f"(hi) : "l"(v));
}
__device__ __forceinline__ float ex2f(float x) {
    float y; asm("ex2.approx.ftz.f32 %0, %1;" : "=f"(y) : "f"(x)); return y;
}
#define FMA2(d, a, b, c) asm("fma.rn.f32x2 %0, %1, %2, %3;" : "=l"(d) : "l"(a), "l"(b), "l"(c))
#define MUL2(d, a, b)    asm("mul.rn.f32x2 %0, %1, %2;"      : "=l"(d) : "l"(a), "l"(b))

// ---------------------------------------------------------------------------
// Dual-c routing pass: processes c0 = w and c1 = w+16 in ONE j-loop so the
// two independent dependency chains (LDS -> dot -> ex2 -> shfl -> rcp) overlap.
// Lanes 0-15 handle o 0-4, lanes 16-31 o 5-9; wv comes from SMEM as broadcast
// LDS.128 per j (keeps fixed register set at Sp[40] = 80 regs).
// Epilogue: JOINT 80-value split-butterfly (80 shfl), all 16 lanes store.
// ---------------------------------------------------------------------------
__device__ __forceinline__ void route_both(const float* __restrict__ u_s,
                                           const float* __restrict__ Wv,
                                           float* __restrict__ S_s,
                                           int c0, int c1, int l16, int half)
{
    const ulonglong2* wv0 =
        reinterpret_cast<const ulonglong2*>(Wv + c0 * 80 + half * 40);
    const ulonglong2* wv1 =
        reinterpret_cast<const ulonglong2*>(Wv + c1 * 80 + half * 40);

    u64p Sp[40];                              // [0:20) = c0, [20:40) = c1
#pragma unroll
    for (int z = 0; z < 40; ++z) Sp[z] = 0ULL;

    const ulonglong2* ub0 =
        reinterpret_cast<const ulonglong2*>(u_s + c0 * U_STRIDE + l16 * Q_SZ);
    const ulonglong2* ub1 =
        reinterpret_cast<const ulonglong2*>(u_s + c1 * U_STRIDE + l16 * Q_SZ);

#pragma unroll 1
    for (int j = 0; j < 9; ++j) {
        // chain A and chain B u loads (independent)
        const ulonglong2 a0 = ub0[j * 32];
        const ulonglong2 b0 = ub0[j * 32 + 1];
        const ulonglong2 a1 = ub1[j * 32];
        const ulonglong2 b1 = ub1[j * 32 + 1];

        float ex0[5], ex1[5];
#pragma unroll
        for (int o = 0; o < 5; ++o) {
            const ulonglong2 w01 = wv0[o * 2];
            const ulonglong2 w23 = wv0[o * 2 + 1];
            u64p t;
            MUL2(t, a0.x, w01.x);
            FMA2(t, a0.y, w01.y, t);
            FMA2(t, b0.x, w23.x, t);
            FMA2(t, b0.y, w23.y, t);
            float lo, hi; upk2(t, lo, hi);
            ex0[o] = ex2f(lo + hi);

            const ulonglong2 x01 = wv1[o * 2];
            const ulonglong2 x23 = wv1[o * 2 + 1];
            u64p s;
            MUL2(s, a1.x, x01.x);
            FMA2(s, a1.y, x01.y, s);
            FMA2(s, b1.x, x23.x, s);
            FMA2(s, b1.y, x23.y, s);
            float lo2, hi2; upk2(s, lo2, hi2);
            ex1[o] = ex2f(lo2 + hi2);
        }

        const float sa0 = ((ex0[0] + ex0[1]) + (ex0[2] + ex0[3])) + ex0[4];
        const float sa1 = ((ex1[0] + ex1[1]) + (ex1[2] + ex1[3])) + ex1[4];
        const float sb0 = __shfl_xor_sync(0xffffffffu, sa0, 16);
        const float sb1 = __shfl_xor_sync(0xffffffffu, sa1, 16);
        const float r0  = __fdividef(1.f, sa0 + sb0);
        const float r1  = __fdividef(1.f, sa1 + sb1);

#pragma unroll
        for (int o = 0; o < 5; ++o) {
            const float ce0 = ex0[o] * r0;
            const u64p cp0 = pk2(ce0, ce0);
            FMA2(Sp[4*o+0], cp0, a0.x, Sp[4*o+0]);
            FMA2(Sp[4*o+1], cp0, a0.y, Sp[4*o+1]);
            FMA2(Sp[4*o+2], cp0, b0.x, Sp[4*o+2]);
            FMA2(Sp[4*o+3], cp0, b0.y, Sp[4*o+3]);

            const float ce1 = ex1[o] * r1;
            const u64p cp1 = pk2(ce1, ce1);
            FMA2(Sp[20+4*o+0], cp1, a1.x, Sp[20+4*o+0]);
            FMA2(Sp[20+4*o+1], cp1, a1.y, Sp[20+4*o+1]);
            FMA2(Sp[20+4*o+2], cp1, b1.x, Sp[20+4*o+2]);
            FMA2(Sp[20+4*o+3], cp1, b1.y, Sp[20+4*o+3]);
        }
    }

    // joint split-butterfly over 80 values ([0:40)=c0, [40:80)=c1)
    float v[80];
#pragma unroll
    for (int z = 0; z < 40; ++z) upk2(Sp[z], v[2*z], v[2*z+1]);
    // note: Sp was [c0:0..19 | c1:20..39] in u64p; in float: c0 = v[0:40), c1 = v[40:80)

    int base = 0;
    {
        const bool up = (l16 & 1);
#pragma unroll
        for (int z = 0; z < 40; ++z) {
            float keep = up ? v[40 + z] : v[z];
            float give = up ? v[z] : v[40 + z];
            v[z] = keep + __shfl_xor_sync(0xffffffffu, give, 1);
        }
        if (up) base += 40;
    }
    {
        const bool up = (l16 & 2);
#pragma unroll
        for (int z = 0; z < 20; ++z) {
            float keep = up ? v[20 + z] : v[z];
            float give = up ? v[z] : v[20 + z];
            v[z] = keep + __shfl_xor_sync(0xffffffffu, give, 2);
        }
        if (up) base += 20;
    }
    {
        const bool up = (l16 & 4);
#pragma unroll
        for (int z = 0; z < 10; ++z) {
            float keep = up ? v[10 + z] : v[z];
            float give = up ? v[z] : v[10 + z];
            v[z] = keep + __shfl_xor_sync(0xffffffffu, give, 4);
        }
        if (up) base += 10;
    }
    {
        const bool up = (l16 & 8);
#pragma unroll
        for (int z = 0; z < 5; ++z) {
            float keep = up ? v[5 + z] : v[z];
            float give = up ? v[z] : v[5 + z];
            v[z] = keep + __shfl_xor_sync(0xffffffffu, give, 8);
        }
        if (up) base += 5;
    }

    // lane owns 5 values at global index [base, base+5); base is a multiple
    // of 5 so the chunk never straddles the c0/c1 boundary at 40.
    {
        const int cc  = (base < 40) ? c0 : c1;
        const int idx = (base < 40) ? base : (base - 40);
        float* dst = S_s + cc * 80 + half * 40 + idx;
#pragma unroll
        for (int z = 0; z < 5; ++z) dst[z] = v[z];
    }
}

// ---------------------------------------------------------------------------
// Fused contract + squash + v_b, warp-cooperative (unchanged from round 9).
// ---------------------------------------------------------------------------
template <bool PER_O, bool LAST>
__device__ __forceinline__ void contract_v(const float* __restrict__ Wg,
                                           const float* __restrict__ S_s,
                                           float* __restrict__ s_b,
                                           float* __restrict__ v_b,
                                           int w, int lane)
{
    if (w < 10) {
        const int o = w;
        const int p = lane & 15;
        const int h = lane >> 4;
        const float* wbase = Wg + o * 128 + p * 8 + h * 4;
        float a0 = 0.f, a1 = 0.f, a2 = 0.f, a3 = 0.f;
#pragma unroll 8
        for (int c = 0; c < 32; ++c) {
            const float4 w4 = *reinterpret_cast<const float4*>(wbase + c * 1280);
            const float4 s4 = *reinterpret_cast<const float4*>(
                S_s + (PER_O ? (c * 80 + o * 8 + h * 4) : (c * 8 + h * 4)));
            a0 += w4.x * s4.x; a1 += w4.y * s4.y;
            a2 += w4.z * s4.z; a3 += w4.w * s4.w;
        }
        float s = (a0 + a1) + (a2 + a3);
        s += __shfl_xor_sync(0xffffffffu, s, 16);

        float sq = s * s;
        sq += __shfl_xor_sync(0xffffffffu, sq, 1);
        sq += __shfl_xor_sync(0xffffffffu, sq, 2);
        sq += __shfl_xor_sync(0xffffffffu, sq, 4);
        sq += __shfl_xor_sync(0xffffffffu, sq, 8);

        if (LAST) {
            const float sc = __fdividef(__fsqrt_rn(sq), 1.f + sq);
            if (h == 0) s_b[o * 16 + p] = s * sc;
        } else {
            const float sc = __fdividef(__fsqrt_rn(sq) * LOG2E, 1.f + sq);
            if (h == 0) v_b[o * 16 + p] = s * sc;
        }
    }
}

// ---------------------------------------------------------------------------
// Warp-cooperative Wv (unchanged from round 9): coalesced W reads.
// ---------------------------------------------------------------------------
template <bool ACC>
__device__ __forceinline__ void compute_Wv_coop(const float* __restrict__ Wg,
                                                const float* __restrict__ v_b,
                                                float* __restrict__ Wv,
                                                int w, int lane)
{
    const int q  = lane & 7;
    const int pg = lane >> 3;
#pragma unroll 5
    for (int m = 0; m < 20; ++m) {
        const int pair = w * 20 + m;          // 0..319
        const int c = pair / 10;
        const int o = pair - c * 10;
        const float* wrow = Wg + c * 1280 + o * 128;
        const float* vrow = v_b + o * 16 + pg;
        float acc = wrow[lane]       * vrow[0]
                  + wrow[32 + lane]  * vrow[4]
                  + wrow[64 + lane]  * vrow[8]
                  + wrow[96 + lane]  * vrow[12];
        acc += __shfl_xor_sync(0xffffffffu, acc, 8);
        acc += __shfl_xor_sync(0xffffffffu, acc, 16);
        if (lane < 8) {
            float* dst = Wv + c * 80 + o * 8 + q;
            *dst = ACC ? (*dst + acc) : acc;
        }
    }
}

__global__ __launch_bounds__(BDIM, 1)
void caps_routing_kernel(const float* __restrict__ xg,
                         const float* __restrict__ Wg,
                         float* __restrict__ outg)
{
    extern __shared__ float sm[];
    float* u_s = sm + U_OFF;
    float* Wv  = sm + WV_OFF;
    float* S_s = sm + S_OFF;
    float* s_b = sm + SB_OFF;
    float* v_b = sm + VB_OFF;

    const int b    = blockIdx.x;
    const int tid  = threadIdx.x;
    const int w    = tid >> 5;
    const int lane = tid & 31;
    const int l16  = lane & 15;
    const int half = lane >> 4;

    // ---- fused load + iteration 0 partial sums (c_ij = 1/10) ----
#pragma unroll
    for (int ci = 0; ci < 2; ++ci) {
        const int c = w + 16 * ci;
        const float4* src =
            reinterpret_cast<const float4*>(xg + (size_t)b * 36864 + c * 1152);
        float4* dst = reinterpret_cast<float4*>(u_s + c * U_STRIDE);
        float4 acc = make_float4(0.f, 0.f, 0.f, 0.f);
#pragma unroll
        for (int k = 0; k < 9; ++k) {
            float4 t = src[lane + 32 * k];
            dst[lane + 32 * k] = t;
            acc.x += t.x; acc.y += t.y; acc.z += t.z; acc.w += t.w;
        }
#pragma unroll
        for (int msk = 2; msk <= 16; msk <<= 1) {
            acc.x += __shfl_xor_sync(0xffffffffu, acc.x, msk);
            acc.y += __shfl_xor_sync(0xffffffffu, acc.y, msk);
            acc.z += __shfl_xor_sync(0xffffffffu, acc.z, msk);
            acc.w += __shfl_xor_sync(0xffffffffu, acc.w, msk);
        }
        if (lane < 2) {    // lane0 -> q0-3, lane1 -> q4-7
            float4* so = reinterpret_cast<float4*>(S_s + c * 8 + lane * 4);
            so[0] = make_float4(acc.x * 0.1f, acc.y * 0.1f, acc.z * 0.1f, acc.w * 0.1f);
        }
    }
    __syncthreads();

    // ---- iteration 0: contract + squash + v_b, then Wv(v0)
    contract_v<false, false>(Wg, S_s, s_b, v_b, w, lane);
    __syncthreads();
    compute_Wv_coop<false>(Wg, v_b, Wv, w, lane);
    __syncthreads();

    // ---- iteration 1
    route_both(u_s, Wv, S_s, w, w + 16, l16, half);
    __syncthreads();
    contract_v<true, false>(Wg, S_s, s_b, v_b, w, lane);
    __syncthreads();
    compute_Wv_coop<true>(Wg, v_b, Wv, w, lane);
    __syncthreads();

    // ---- iteration 2
    route_both(u_s, Wv, S_s, w, w + 16, l16, half);
    __syncthreads();
    contract_v<true, true>(Wg, S_s, s_b, v_b, w, lane);   // writes squashed v -> s_b
    __syncthreads();

    if (tid < 160) outg[b * 160 + tid] = s_b[tid];
}

extern "C" void kernel_launch(void* const* d_in, const int* in_sizes, int n_in,
                              void* d_out, int out_size)
{
    const float* x = (const float*)d_in[0];
    const float* W = (const float*)d_in[1];
    if (n_in >= 2 && in_sizes[0] < in_sizes[1]) {
        const float* t = x; x = W; W = t;
    }
    (void)out_size;

    cudaFuncSetAttribute(caps_routing_kernel,
                         cudaFuncAttributeMaxDynamicSharedMemorySize, SMEM_BYTES);
    caps_routing_kernel<<<B_SZ, BDIM, SMEM_BYTES>>>(x, W, (float*)d_out);
}

// round 13
// speedup vs baseline: 1.7091x; 1.7091x over previous
#include <cuda_runtime.h>
#include <math.h>

#define B_SZ   128
#define Q_SZ   8
#define BDIM   512

#define U_STRIDE 1152

// SMEM layout (floats)
#define U_OFF   0
#define U_SIZE  (32 * U_STRIDE)             // 36864
#define WV_OFF  U_SIZE                       // Wv  [32][10][8] = 2560 (accumulated, log2e-scaled)
#define S_OFF   (WV_OFF + 2560)              // S_s [32][10][8] = 2560 (iter0: [32][8])
#define SB_OFF  (S_OFF + 2560)               // s_b [10][16] = 160 (final squashed v)
#define VB_OFF  (SB_OFF + 160)               // v_b [10][16] = 160 (log2e-scaled v)
#define SMEM_FLOATS (VB_OFF + 160)
#define SMEM_BYTES  (SMEM_FLOATS * 4)

#define LOG2E 1.4426950408889634f

typedef unsigned long long u64p;             // packed f32x2

__device__ __forceinline__ u64p pk2(float lo, float hi) {
    u64p r; asm("mov.b64 %0, {%1, %2};" : "=l"(r) : "f"(lo), "f"(hi)); return r;
}
__device__ __forceinline__ void upk2(u64p v, float& lo, float& hi) {
    asm("mov.b64 {%0, %1}, %2;" : "=f"(lo), "=f"(hi) : "l"(v));
}
__device__ __forceinline__ float ex2f(float x) {
    float y; asm("ex2.approx.ftz.f32 %0, %1;" : "=f"(y) : "f"(x)); return y;
}
#define FMA2(d, a, b, c) asm("fma.rn.f32x2 %0, %1, %2, %3;" : "=l"(d) : "l"(a), "l"(b), "l"(c))
#define MUL2(d, a, b)    asm("mul.rn.f32x2 %0, %1, %2;"      : "=l"(d) : "l"(a), "l"(b))

// ---------------------------------------------------------------------------
// Routing pass for one c (round-9 proven variant): lanes 0-15 o 0-4,
// lanes 16-31 o 5-9; wv from SMEM as broadcast LDS; no-max log2 softmax.
// ---------------------------------------------------------------------------
__device__ __forceinline__ void route_c(const float* __restrict__ u_s,
                                        const float* __restrict__ Wv,
                                        float* __restrict__ S_s,
                                        int c, int l16, int half)
{
    const ulonglong2* wvp =
        reinterpret_cast<const ulonglong2*>(Wv + c * 80 + half * 40);

    u64p Sp[20];
#pragma unroll
    for (int z = 0; z < 20; ++z) Sp[z] = 0ULL;

    const ulonglong2* ub =
        reinterpret_cast<const ulonglong2*>(u_s + c * U_STRIDE + l16 * Q_SZ);

    ulonglong2 ua = ub[0];
    ulonglong2 uc = ub[1];

#pragma unroll 2
    for (int j = 0; j < 9; ++j) {
        const u64p uq0 = ua.x, uq1 = ua.y, uq2 = uc.x, uq3 = uc.y;
        if (j < 8) {
            ua = ub[(j + 1) * 32];
            uc = ub[(j + 1) * 32 + 1];
        }

        float ex[5];
#pragma unroll
        for (int o = 0; o < 5; ++o) {
            const ulonglong2 w01 = wvp[o * 2];
            const ulonglong2 w23 = wvp[o * 2 + 1];
            u64p t;
            MUL2(t, uq0, w01.x);
            FMA2(t, uq1, w01.y, t);
            FMA2(t, uq2, w23.x, t);
            FMA2(t, uq3, w23.y, t);
            float lo, hi; upk2(t, lo, hi);
            ex[o] = ex2f(lo + hi);
        }
        const float sa = ((ex[0] + ex[1]) + (ex[2] + ex[3])) + ex[4];
        const float sb = __shfl_xor_sync(0xffffffffu, sa, 16);
        const float r  = __fdividef(1.f, sa + sb);

#pragma unroll
        for (int o = 0; o < 5; ++o) {
            const float ce = ex[o] * r;
            const u64p cep = pk2(ce, ce);
            FMA2(Sp[4*o+0], cep, uq0, Sp[4*o+0]);
            FMA2(Sp[4*o+1], cep, uq1, Sp[4*o+1]);
            FMA2(Sp[4*o+2], cep, uq2, Sp[4*o+2]);
            FMA2(Sp[4*o+3], cep, uq3, Sp[4*o+3]);
        }
    }

    float v[40];
#pragma unroll
    for (int z = 0; z < 20; ++z) upk2(Sp[z], v[2*z], v[2*z+1]);

    int base = 0;
    {
        const bool up = (l16 & 1);
#pragma unroll
        for (int z = 0; z < 20; ++z) {
            float keep = up ? v[20 + z] : v[z];
            float give = up ? v[z] : v[20 + z];
            v[z] = keep + __shfl_xor_sync(0xffffffffu, give, 1);
        }
        if (up) base += 20;
    }
    {
        const bool up = (l16 & 2);
#pragma unroll
        for (int z = 0; z < 10; ++z) {
            float keep = up ? v[10 + z] : v[z];
            float give = up ? v[z] : v[10 + z];
            v[z] = keep + __shfl_xor_sync(0xffffffffu, give, 2);
        }
        if (up) base += 10;
    }
    {
        const bool up = (l16 & 4);
#pragma unroll
        for (int z = 0; z < 5; ++z) {
            float keep = up ? v[5 + z] : v[z];
            float give = up ? v[z] : v[5 + z];
            v[z] = keep + __shfl_xor_sync(0xffffffffu, give, 4);
        }
        if (up) base += 5;
    }
#pragma unroll
    for (int z = 0; z < 5; ++z)
        v[z] += __shfl_xor_sync(0xffffffffu, v[z], 8);

    if ((l16 & 8) == 0) {
        float* dst = S_s + c * 80 + half * 40 + base;
#pragma unroll
        for (int z = 0; z < 5; ++z) dst[z] = v[z];
    }
}

// ---------------------------------------------------------------------------
// Fused contract + squash + v_b, warp-cooperative. Warp w < 10 owns o = w.
// unroll 16 -> 16 outstanding LDG (halves exposed L2 latency vs unroll 8).
// ---------------------------------------------------------------------------
template <bool PER_O, bool LAST>
__device__ __forceinline__ void contract_v(const float* __restrict__ Wg,
                                           const float* __restrict__ S_s,
                                           float* __restrict__ s_b,
                                           float* __restrict__ v_b,
                                           int w, int lane)
{
    if (w < 10) {
        const int o = w;
        const int p = lane & 15;
        const int h = lane >> 4;
        const float* wbase = Wg + o * 128 + p * 8 + h * 4;
        float a0 = 0.f, a1 = 0.f, a2 = 0.f, a3 = 0.f;
#pragma unroll 16
        for (int c = 0; c < 32; ++c) {
            const float4 w4 = *reinterpret_cast<const float4*>(wbase + c * 1280);
            const float4 s4 = *reinterpret_cast<const float4*>(
                S_s + (PER_O ? (c * 80 + o * 8 + h * 4) : (c * 8 + h * 4)));
            a0 += w4.x * s4.x; a1 += w4.y * s4.y;
            a2 += w4.z * s4.z; a3 += w4.w * s4.w;
        }
        float s = (a0 + a1) + (a2 + a3);
        s += __shfl_xor_sync(0xffffffffu, s, 16);     // combine q-halves

        float sq = s * s;
        sq += __shfl_xor_sync(0xffffffffu, sq, 1);
        sq += __shfl_xor_sync(0xffffffffu, sq, 2);
        sq += __shfl_xor_sync(0xffffffffu, sq, 4);
        sq += __shfl_xor_sync(0xffffffffu, sq, 8);    // ||s||^2 over 16 p-lanes

        if (LAST) {
            const float sc = __fdividef(__fsqrt_rn(sq), 1.f + sq);
            if (h == 0) s_b[o * 16 + p] = s * sc;
        } else {
            const float sc = __fdividef(__fsqrt_rn(sq) * LOG2E, 1.f + sq);
            if (h == 0) v_b[o * 16 + p] = s * sc;
        }
    }
}

// ---------------------------------------------------------------------------
// Warp-cooperative Wv: all 16 warps, 20 (c,o) pairs each, coalesced W reads.
// pair = 20w + m decomposed WITHOUT runtime integer division:
//   c = 2w + (m >= 10),  o = m - 10*(m >= 10)  — compile-time per unrolled m.
// (round 9 used pair/10 at runtime: ~20-instr div emulation x 20 pairs x 3
//  phases of pure ALU waste — this was the measured alu=13%.)
// ---------------------------------------------------------------------------
template <bool ACC>
__device__ __forceinline__ void compute_Wv_coop(const float* __restrict__ Wg,
                                                const float* __restrict__ v_b,
                                                float* __restrict__ Wv,
                                                int w, int lane)
{
    const int q   = lane & 7;
    const int pg  = lane >> 3;
    const int c0  = w * 2;
    const float* wbase = Wg + c0 * 1280;
    float* wvbase = Wv + c0 * 80;
#pragma unroll
    for (int m = 0; m < 20; ++m) {
        const int dc = (m >= 10) ? 1 : 0;     // compile-time per m
        const int o  = m - 10 * dc;           // compile-time per m
        const float* wrow = wbase + dc * 1280 + o * 128;
        const float* vrow = v_b + o * 16 + pg;
        float acc = wrow[lane]       * vrow[0]
                  + wrow[32 + lane]  * vrow[4]
                  + wrow[64 + lane]  * vrow[8]
                  + wrow[96 + lane]  * vrow[12];
        acc += __shfl_xor_sync(0xffffffffu, acc, 8);
        acc += __shfl_xor_sync(0xffffffffu, acc, 16);
        if (lane < 8) {
            float* dst = wvbase + dc * 80 + o * 8 + q;
            *dst = ACC ? (*dst + acc) : acc;
        }
    }
}

__global__ __launch_bounds__(BDIM, 1)
void caps_routing_kernel(const float* __restrict__ xg,
                         const float* __restrict__ Wg,
                         float* __restrict__ outg)
{
    extern __shared__ float sm[];
    float* u_s = sm + U_OFF;
    float* Wv  = sm + WV_OFF;
    float* S_s = sm + S_OFF;
    float* s_b = sm + SB_OFF;
    float* v_b = sm + VB_OFF;

    const int b    = blockIdx.x;
    const int tid  = threadIdx.x;
    const int w    = tid >> 5;
    const int lane = tid & 31;
    const int l16  = lane & 15;
    const int half = lane >> 4;

    // ---- fused load + iteration 0 partial sums (c_ij = 1/10) ----
#pragma unroll
    for (int ci = 0; ci < 2; ++ci) {
        const int c = w + 16 * ci;
        const float4* src =
            reinterpret_cast<const float4*>(xg + (size_t)b * 36864 + c * 1152);
        float4* dst = reinterpret_cast<float4*>(u_s + c * U_STRIDE);
        float4 acc = make_float4(0.f, 0.f, 0.f, 0.f);
#pragma unroll
        for (int k = 0; k < 9; ++k) {
            float4 t = src[lane + 32 * k];
            dst[lane + 32 * k] = t;
            acc.x += t.x; acc.y += t.y; acc.z += t.z; acc.w += t.w;
        }
#pragma unroll
        for (int msk = 2; msk <= 16; msk <<= 1) {
            acc.x += __shfl_xor_sync(0xffffffffu, acc.x, msk);
            acc.y += __shfl_xor_sync(0xffffffffu, acc.y, msk);
            acc.z += __shfl_xor_sync(0xffffffffu, acc.z, msk);
            acc.w += __shfl_xor_sync(0xffffffffu, acc.w, msk);
        }
        if (lane < 2) {    // lane0 -> q0-3, lane1 -> q4-7
            float4* so = reinterpret_cast<float4*>(S_s + c * 8 + lane * 4);
            so[0] = make_float4(acc.x * 0.1f, acc.y * 0.1f, acc.z * 0.1f, acc.w * 0.1f);
        }
    }
    __syncthreads();

    // ---- iteration 0: contract + squash + v_b, then Wv(v0)
    contract_v<false, false>(Wg, S_s, s_b, v_b, w, lane);
    __syncthreads();
    compute_Wv_coop<false>(Wg, v_b, Wv, w, lane);
    __syncthreads();

    // ---- iteration 1
    route_c(u_s, Wv, S_s, w, l16, half);
    route_c(u_s, Wv, S_s, w + 16, l16, half);
    __syncthreads();
    contract_v<true, false>(Wg, S_s, s_b, v_b, w, lane);
    __syncthreads();
    compute_Wv_coop<true>(Wg, v_b, Wv, w, lane);
    __syncthreads();

    // ---- iteration 2
    route_c(u_s, Wv, S_s, w, l16, half);
    route_c(u_s, Wv, S_s, w + 16, l16, half);
    __syncthreads();
    contract_v<true, true>(Wg, S_s, s_b, v_b, w, lane);   // writes squashed v -> s_b
    __syncthreads();

    if (tid < 160) outg[b * 160 + tid] = s_b[tid];
}

extern "C" void kernel_launch(void* const* d_in, const int* in_sizes, int n_in,
                              void* d_out, int out_size)
{
    const float* x = (const float*)d_in[0];
    const float* W = (const float*)d_in[1];
    if (n_in >= 2 && in_sizes[0] < in_sizes[1]) {
        const float* t = x; x = W; W = t;
    }
    (void)out_size;

    cudaFuncSetAttribute(caps_routing_kernel,
                         cudaFuncAttributeMaxDynamicSharedMemorySize, SMEM_BYTES);
    caps_routing_kernel<<<B_SZ, BDIM, SMEM_BYTES>>>(x, W, (float*)d_out);
}

// round 14
// speedup vs baseline: 1.7213x; 1.0072x over previous
#include <cuda_runtime.h>
#include <math.h>

#define B_SZ   128
#define Q_SZ   8
#define BDIM   512

#define U_STRIDE 1152

// SMEM layout (floats)
#define U_OFF   0
#define U_SIZE  (32 * U_STRIDE)             // 36864
#define WV_OFF  U_SIZE                       // Wv  [32][10][8] = 2560 (accumulated, log2e-scaled)
#define S_OFF   (WV_OFF + 2560)              // S_s [32][10][8] = 2560 (iter0: [32][8])
#define SB_OFF  (S_OFF + 2560)               // s_b [10][16] = 160 (final squashed v)
#define VB_OFF  (SB_OFF + 160)               // v_b [10][16] = 160 (log2e-scaled v)
#define SMEM_FLOATS (VB_OFF + 160)
#define SMEM_BYTES  (SMEM_FLOATS * 4)

#define LOG2E 1.4426950408889634f

typedef unsigned long long u64p;             // packed f32x2

__device__ __forceinline__ u64p pk2(float lo, float hi) {
    u64p r; asm("mov.b64 %0, {%1, %2};" : "=l"(r) : "f"(lo), "f"(hi)); return r;
}
__device__ __forceinline__ void upk2(u64p v, float& lo, float& hi) {
    asm("mov.b64 {%0, %1}, %2;" : "=f"(lo), "=f"(hi) : "l"(v));
}
__device__ __forceinline__ float ex2f(float x) {
    float y; asm("ex2.approx.ftz.f32 %0, %1;" : "=f"(y) : "f"(x)); return y;
}
#define FMA2(d, a, b, c) asm("fma.rn.f32x2 %0, %1, %2, %3;" : "=l"(d) : "l"(a), "l"(b), "l"(c))
#define MUL2(d, a, b)    asm("mul.rn.f32x2 %0, %1, %2;"      : "=l"(d) : "l"(a), "l"(b))

// ---------------------------------------------------------------------------
// Routing pass for one c, DUAL-POINT inner loop: lanes 0-15 handle o 0-4,
// lanes 16-31 o 5-9. Each iteration a lane processes TWO spatial points
// (j*32+l16 and j*32+16+l16) -> two independent softmax chains that share
// the same wv broadcast loads and the same Sp accumulators. 144 = 4*32 + 16
// tail. wv stays in SMEM (broadcast LDS), Sp fixed at 20 u64p (40 regs).
// ---------------------------------------------------------------------------
__device__ __forceinline__ void route_c(const float* __restrict__ u_s,
                                        const float* __restrict__ Wv,
                                        float* __restrict__ S_s,
                                        int c, int l16, int half)
{
    const ulonglong2* wvp =
        reinterpret_cast<const ulonglong2*>(Wv + c * 80 + half * 40);

    u64p Sp[20];
#pragma unroll
    for (int z = 0; z < 20; ++z) Sp[z] = 0ULL;

    const ulonglong2* ub =
        reinterpret_cast<const ulonglong2*>(u_s + c * U_STRIDE + l16 * Q_SZ);

#pragma unroll 1
    for (int j = 0; j < 4; ++j) {
        // point A = j*32 + l16, point B = j*32 + 16 + l16
        const ulonglong2 a01 = ub[j * 64];
        const ulonglong2 a23 = ub[j * 64 + 1];
        const ulonglong2 b01 = ub[j * 64 + 32];
        const ulonglong2 b23 = ub[j * 64 + 33];

        float exa[5], exb[5];
#pragma unroll
        for (int o = 0; o < 5; ++o) {
            const ulonglong2 w01 = wvp[o * 2];      // broadcast LDS, shared by A & B
            const ulonglong2 w23 = wvp[o * 2 + 1];
            u64p ta, tb;
            MUL2(ta, a01.x, w01.x);
            MUL2(tb, b01.x, w01.x);
            FMA2(ta, a01.y, w01.y, ta);
            FMA2(tb, b01.y, w01.y, tb);
            FMA2(ta, a23.x, w23.x, ta);
            FMA2(tb, b23.x, w23.x, tb);
            FMA2(ta, a23.y, w23.y, ta);
            FMA2(tb, b23.y, w23.y, tb);
            float la, ha, lb, hb;
            upk2(ta, la, ha);
            upk2(tb, lb, hb);
            exa[o] = ex2f(la + ha);
            exb[o] = ex2f(lb + hb);
        }
        const float sa = ((exa[0] + exa[1]) + (exa[2] + exa[3])) + exa[4];
        const float sb = ((exb[0] + exb[1]) + (exb[2] + exb[3])) + exb[4];
        const float sao = __shfl_xor_sync(0xffffffffu, sa, 16);
        const float sbo = __shfl_xor_sync(0xffffffffu, sb, 16);
        const float ra = __fdividef(1.f, sa + sao);
        const float rb = __fdividef(1.f, sb + sbo);

#pragma unroll
        for (int o = 0; o < 5; ++o) {
            const float cea = exa[o] * ra;
            const float ceb = exb[o] * rb;
            const u64p cpa = pk2(cea, cea);
            const u64p cpb = pk2(ceb, ceb);
            FMA2(Sp[4*o+0], cpa, a01.x, Sp[4*o+0]);
            FMA2(Sp[4*o+1], cpa, a01.y, Sp[4*o+1]);
            FMA2(Sp[4*o+2], cpa, a23.x, Sp[4*o+2]);
            FMA2(Sp[4*o+3], cpa, a23.y, Sp[4*o+3]);
            FMA2(Sp[4*o+0], cpb, b01.x, Sp[4*o+0]);
            FMA2(Sp[4*o+1], cpb, b01.y, Sp[4*o+1]);
            FMA2(Sp[4*o+2], cpb, b23.x, Sp[4*o+2]);
            FMA2(Sp[4*o+3], cpb, b23.y, Sp[4*o+3]);
        }
    }

    // tail: single point 128 + l16  (ulonglong2 index 128*2 = 256)
    {
        const ulonglong2 a01 = ub[256];
        const ulonglong2 a23 = ub[257];
        float ex[5];
#pragma unroll
        for (int o = 0; o < 5; ++o) {
            const ulonglong2 w01 = wvp[o * 2];
            const ulonglong2 w23 = wvp[o * 2 + 1];
            u64p t;
            MUL2(t, a01.x, w01.x);
            FMA2(t, a01.y, w01.y, t);
            FMA2(t, a23.x, w23.x, t);
            FMA2(t, a23.y, w23.y, t);
            float lo, hi; upk2(t, lo, hi);
            ex[o] = ex2f(lo + hi);
        }
        const float sa = ((ex[0] + ex[1]) + (ex[2] + ex[3])) + ex[4];
        const float sb = __shfl_xor_sync(0xffffffffu, sa, 16);
        const float r  = __fdividef(1.f, sa + sb);
#pragma unroll
        for (int o = 0; o < 5; ++o) {
            const float ce = ex[o] * r;
            const u64p cep = pk2(ce, ce);
            FMA2(Sp[4*o+0], cep, a01.x, Sp[4*o+0]);
            FMA2(Sp[4*o+1], cep, a01.y, Sp[4*o+1]);
            FMA2(Sp[4*o+2], cep, a23.x, Sp[4*o+2]);
            FMA2(Sp[4*o+3], cep, a23.y, Sp[4*o+3]);
        }
    }

    // unpack and split-butterfly reduce 40 values over the 16 spatial lanes
    float v[40];
#pragma unroll
    for (int z = 0; z < 20; ++z) upk2(Sp[z], v[2*z], v[2*z+1]);

    int base = 0;
    {
        const bool up = (l16 & 1);
#pragma unroll
        for (int z = 0; z < 20; ++z) {
            float keep = up ? v[20 + z] : v[z];
            float give = up ? v[z] : v[20 + z];
            v[z] = keep + __shfl_xor_sync(0xffffffffu, give, 1);
        }
        if (up) base += 20;
    }
    {
        const bool up = (l16 & 2);
#pragma unroll
        for (int z = 0; z < 10; ++z) {
            float keep = up ? v[10 + z] : v[z];
            float give = up ? v[z] : v[10 + z];
            v[z] = keep + __shfl_xor_sync(0xffffffffu, give, 2);
        }
        if (up) base += 10;
    }
    {
        const bool up = (l16 & 4);
#pragma unroll
        for (int z = 0; z < 5; ++z) {
            float keep = up ? v[5 + z] : v[z];
            float give = up ? v[z] : v[5 + z];
            v[z] = keep + __shfl_xor_sync(0xffffffffu, give, 4);
        }
        if (up) base += 5;
    }
#pragma unroll
    for (int z = 0; z < 5; ++z)
        v[z] += __shfl_xor_sync(0xffffffffu, v[z], 8);

    if ((l16 & 8) == 0) {
        float* dst = S_s + c * 80 + half * 40 + base;
#pragma unroll
        for (int z = 0; z < 5; ++z) dst[z] = v[z];
    }
}

// ---------------------------------------------------------------------------
// Fused contract + squash + v_b, warp-cooperative (round 13). Warp w<10 owns
// o=w; unroll 16 keeps 16 LDG outstanding against L2.
// ---------------------------------------------------------------------------
template <bool PER_O, bool LAST>
__device__ __forceinline__ void contract_v(const float* __restrict__ Wg,
                                           const float* __restrict__ S_s,
                                           float* __restrict__ s_b,
                                           float* __restrict__ v_b,
                                           int w, int lane)
{
    if (w < 10) {
        const int o = w;
        const int p = lane & 15;
        const int h = lane >> 4;
        const float* wbase = Wg + o * 128 + p * 8 + h * 4;
        float a0 = 0.f, a1 = 0.f, a2 = 0.f, a3 = 0.f;
#pragma unroll 16
        for (int c = 0; c < 32; ++c) {
            const float4 w4 = *reinterpret_cast<const float4*>(wbase + c * 1280);
            const float4 s4 = *reinterpret_cast<const float4*>(
                S_s + (PER_O ? (c * 80 + o * 8 + h * 4) : (c * 8 + h * 4)));
            a0 += w4.x * s4.x; a1 += w4.y * s4.y;
            a2 += w4.z * s4.z; a3 += w4.w * s4.w;
        }
        float s = (a0 + a1) + (a2 + a3);
        s += __shfl_xor_sync(0xffffffffu, s, 16);     // combine q-halves

        float sq = s * s;
        sq += __shfl_xor_sync(0xffffffffu, sq, 1);
        sq += __shfl_xor_sync(0xffffffffu, sq, 2);
        sq += __shfl_xor_sync(0xffffffffu, sq, 4);
        sq += __shfl_xor_sync(0xffffffffu, sq, 8);    // ||s||^2 over 16 p-lanes

        if (LAST) {
            const float sc = __fdividef(__fsqrt_rn(sq), 1.f + sq);
            if (h == 0) s_b[o * 16 + p] = s * sc;
        } else {
            const float sc = __fdividef(__fsqrt_rn(sq) * LOG2E, 1.f + sq);
            if (h == 0) v_b[o * 16 + p] = s * sc;
        }
    }
}

// ---------------------------------------------------------------------------
// Warp-cooperative Wv (round 13): coalesced W reads, no runtime int division.
// ---------------------------------------------------------------------------
template <bool ACC>
__device__ __forceinline__ void compute_Wv_coop(const float* __restrict__ Wg,
                                                const float* __restrict__ v_b,
                                                float* __restrict__ Wv,
                                                int w, int lane)
{
    const int q   = lane & 7;
    const int pg  = lane >> 3;
    const int c0  = w * 2;
    const float* wbase = Wg + c0 * 1280;
    float* wvbase = Wv + c0 * 80;
#pragma unroll
    for (int m = 0; m < 20; ++m) {
        const int dc = (m >= 10) ? 1 : 0;     // compile-time per m
        const int o  = m - 10 * dc;           // compile-time per m
        const float* wrow = wbase + dc * 1280 + o * 128;
        const float* vrow = v_b + o * 16 + pg;
        float acc = wrow[lane]       * vrow[0]
                  + wrow[32 + lane]  * vrow[4]
                  + wrow[64 + lane]  * vrow[8]
                  + wrow[96 + lane]  * vrow[12];
        acc += __shfl_xor_sync(0xffffffffu, acc, 8);
        acc += __shfl_xor_sync(0xffffffffu, acc, 16);
        if (lane < 8) {
            float* dst = wvbase + dc * 80 + o * 8 + q;
            *dst = ACC ? (*dst + acc) : acc;
        }
    }
}

__global__ __launch_bounds__(BDIM, 1)
void caps_routing_kernel(const float* __restrict__ xg,
                         const float* __restrict__ Wg,
                         float* __restrict__ outg)
{
    extern __shared__ float sm[];
    float* u_s = sm + U_OFF;
    float* Wv  = sm + WV_OFF;
    float* S_s = sm + S_OFF;
    float* s_b = sm + SB_OFF;
    float* v_b = sm + VB_OFF;

    const int b    = blockIdx.x;
    const int tid  = threadIdx.x;
    const int w    = tid >> 5;
    const int lane = tid & 31;
    const int l16  = lane & 15;
    const int half = lane >> 4;

    // ---- fused load + iteration 0 partial sums (c_ij = 1/10) ----
#pragma unroll
    for (int ci = 0; ci < 2; ++ci) {
        const int c = w + 16 * ci;
        const float4* src =
            reinterpret_cast<const float4*>(xg + (size_t)b * 36864 + c * 1152);
        float4* dst = reinterpret_cast<float4*>(u_s + c * U_STRIDE);
        float4 acc = make_float4(0.f, 0.f, 0.f, 0.f);
#pragma unroll
        for (int k = 0; k < 9; ++k) {
            float4 t = src[lane + 32 * k];
            dst[lane + 32 * k] = t;
            acc.x += t.x; acc.y += t.y; acc.z += t.z; acc.w += t.w;
        }
#pragma unroll
        for (int msk = 2; msk <= 16; msk <<= 1) {
            acc.x += __shfl_xor_sync(0xffffffffu, acc.x, msk);
            acc.y += __shfl_xor_sync(0xffffffffu, acc.y, msk);
            acc.z += __shfl_xor_sync(0xffffffffu, acc.z, msk);
            acc.w += __shfl_xor_sync(0xffffffffu, acc.w, msk);
        }
        if (lane < 2) {    // lane0 -> q0-3, lane1 -> q4-7
            float4* so = reinterpret_cast<float4*>(S_s + c * 8 + lane * 4);
            so[0] = make_float4(acc.x * 0.1f, acc.y * 0.1f, acc.z * 0.1f, acc.w * 0.1f);
        }
    }
    __syncthreads();

    // ---- iteration 0: contract + squash + v_b, then Wv(v0)
    contract_v<false, false>(Wg, S_s, s_b, v_b, w, lane);
    __syncthreads();
    compute_Wv_coop<false>(Wg, v_b, Wv, w, lane);
    __syncthreads();

    // ---- iteration 1
    route_c(u_s, Wv, S_s, w, l16, half);
    route_c(u_s, Wv, S_s, w + 16, l16, half);
    __syncthreads();
    contract_v<true, false>(Wg, S_s, s_b, v_b, w, lane);
    __syncthreads();
    compute_Wv_coop<true>(Wg, v_b, Wv, w, lane);
    __syncthreads();

    // ---- iteration 2
    route_c(u_s, Wv, S_s, w, l16, half);
    route_c(u_s, Wv, S_s, w + 16, l16, half);
    __syncthreads();
    contract_v<true, true>(Wg, S_s, s_b, v_b, w, lane);   // writes squashed v -> s_b
    __syncthreads();

    if (tid < 160) outg[b * 160 + tid] = s_b[tid];
}

extern "C" void kernel_launch(void* const* d_in, const int* in_sizes, int n_in,
                              void* d_out, int out_size)
{
    const float* x = (const float*)d_in[0];
    const float* W = (const float*)d_in[1];
    if (n_in >= 2 && in_sizes[0] < in_sizes[1]) {
        const float* t = x; x = W; W = t;
    }
    (void)out_size;

    cudaFuncSetAttribute(caps_routing_kernel,
                         cudaFuncAttributeMaxDynamicSharedMemorySize, SMEM_BYTES);
    caps_routing_kernel<<<B_SZ, BDIM, SMEM_BYTES>>>(x, W, (float*)d_out);
}